// round 10
// baseline (speedup 1.0000x reference)
#include <cuda_runtime.h>
#include <math.h>

#define BATCH 512
#define NLAT  16
#define DIM   128
#define ROWS  (BATCH*NLAT)   /* 8192 */

/* ------------------- scratch (no allocations allowed) ------------------- */
__device__ float g_lat [ROWS*DIM];
__device__ float g_nl  [ROWS*DIM];
__device__ float g_qh  [ROWS*DIM];
__device__ float g_qt  [ROWS*512];
__device__ float g_cb  [ROWS*4];
__device__ float g_U   [ROWS*512];
__device__ float g_o   [ROWS*DIM];
__device__ float g_f1  [ROWS*256];
__device__ float g_hh  [BATCH*DIM];
__device__ float g_weff[8*DIM*DIM];
__device__ float g_beff[8*DIM];
__device__ int   g_sd[BATCH], g_ldn[BATCH], g_se[BATCH], g_len[BATCH];

/* ------------------- segment bounds from sorted batch ids --------------- */
__global__ void k_bounds(const int* __restrict__ batch, int n, int maxlen,
                         int* __restrict__ start, int* __restrict__ len)
{
    int b = blockIdx.x * blockDim.x + threadIdx.x;
    if (b >= BATCH) return;
    int lo = 0, hi = n;
    while (lo < hi) { int mid = (lo + hi) >> 1; if (batch[mid] < b) lo = mid + 1; else hi = mid; }
    int s = lo;
    lo = s; hi = n;
    while (lo < hi) { int mid = (lo + hi) >> 1; if (batch[mid] < b + 1) lo = mid + 1; else hi = mid; }
    int L = lo - s;
    if (L > maxlen) L = maxlen;   /* JAX OOB scatter drops tokens beyond maxlen */
    start[b] = s; len[b] = L;
}

__global__ void k_init(const float* __restrict__ latents, float* __restrict__ lat)
{
    int idx = blockIdx.x * blockDim.x + threadIdx.x;
    if (idx < ROWS*DIM) lat[idx] = latents[idx & (NLAT*DIM - 1)];
}

/* ------------------- LayerNorm, one warp per 128-dim row ---------------- */
__global__ void __launch_bounds__(256) k_ln(const float* __restrict__ x,
                                            const float* __restrict__ g,
                                            const float* __restrict__ bt,
                                            float* __restrict__ y, int M)
{
    int row  = blockIdx.x * 8 + (threadIdx.x >> 5);
    int lane = threadIdx.x & 31;
    if (row >= M) return;
    float4 v = *(const float4*)(x + (size_t)row*DIM + lane*4);
    float s = v.x + v.y + v.z + v.w;
#pragma unroll
    for (int o = 16; o > 0; o >>= 1) s += __shfl_xor_sync(0xffffffffu, s, o);
    float m = s * (1.0f/128.0f);
    float d0 = v.x-m, d1 = v.y-m, d2 = v.z-m, d3 = v.w-m;
    float q = d0*d0 + d1*d1 + d2*d2 + d3*d3;
#pragma unroll
    for (int o = 16; o > 0; o >>= 1) q += __shfl_xor_sync(0xffffffffu, q, o);
    float inv = rsqrtf(q * (1.0f/128.0f) + 1e-5f);
    float4 gg = *(const float4*)(g  + lane*4);
    float4 bb = *(const float4*)(bt + lane*4);
    float4 o4;
    o4.x = d0*inv*gg.x + bb.x;  o4.y = d1*inv*gg.y + bb.y;
    o4.z = d2*inv*gg.z + bb.z;  o4.w = d3*inv*gg.w + bb.w;
    *(float4*)(y + (size_t)row*DIM + lane*4) = o4;
}

/* ------------------- generic fp32 GEMM ---------------------------------- */
/* C = act( A[M,K] x op(W) + bias (+C) ).  TRANSW: W stored [N,K].          */
/* blockIdx.z applies batched offsets.  BM=64, BK=32, BN in {32,128}.       */
template<int BN, bool TRANSW, bool BIAS, bool ACC, bool RELU>
__global__ void __launch_bounds__(256)
k_gemm(const float* __restrict__ A, int lda, int aSz,
       const float* __restrict__ W, int ldw, int wSz,
       const float* __restrict__ Bv, int bSz,
       float* __restrict__ C, int ldc, int cSz,
       int M, int K)
{
    constexpr int BM = 64, BK = 32;
    constexpr int TX = BN/4;
    constexpr int TY = 256/TX;
    constexpr int RT = BM/TY;
    constexpr int NA = BM*BK/256;
    constexpr int NW = BN*BK/256;
    __shared__ __align__(16) float As[BK][BM+4];
    __shared__ __align__(16) float Ws[BK][BN+4];

    A += (size_t)blockIdx.z * aSz;
    W += (size_t)blockIdx.z * wSz;
    C += (size_t)blockIdx.z * cSz;
    const float* bias = nullptr;
    if (BIAS) bias = Bv + (size_t)blockIdx.z * bSz;

    int t = threadIdx.x;
    int tx = t % TX, ty = t / TX;
    int mBase = blockIdx.x * BM, nBase = blockIdx.y * BN;

    float acc[RT][4];
#pragma unroll
    for (int r = 0; r < RT; r++) { acc[r][0]=0.f; acc[r][1]=0.f; acc[r][2]=0.f; acc[r][3]=0.f; }

    for (int k0 = 0; k0 < K; k0 += BK) {
#pragma unroll
        for (int u = 0; u < NA; u++) {
            int i = t + u*256;
            int r = i >> 5, c = i & 31;
            As[c][r] = A[(size_t)(mBase + r) * lda + k0 + c];
        }
        if (TRANSW) {
#pragma unroll
            for (int u = 0; u < NW; u++) {
                int i = t + u*256;
                int n = i >> 5, c = i & 31;
                Ws[c][n] = W[(size_t)(nBase + n) * ldw + k0 + c];
            }
        } else {
#pragma unroll
            for (int u = 0; u < NW; u++) {
                int i = t + u*256;
                int c = i / BN, n = i % BN;
                Ws[c][n] = W[(size_t)(k0 + c) * ldw + nBase + n];
            }
        }
        __syncthreads();
#pragma unroll
        for (int kk = 0; kk < BK; kk++) {
            float av[RT];
#pragma unroll
            for (int r = 0; r < RT; r++) av[r] = As[kk][ty*RT + r];
            float4 b4 = *(const float4*)&Ws[kk][tx*4];
#pragma unroll
            for (int r = 0; r < RT; r++) {
                acc[r][0] += av[r]*b4.x; acc[r][1] += av[r]*b4.y;
                acc[r][2] += av[r]*b4.z; acc[r][3] += av[r]*b4.w;
            }
        }
        __syncthreads();
    }

#pragma unroll
    for (int r = 0; r < RT; r++) {
        int m = mBase + ty*RT + r;
        int n = nBase + tx*4;
        float4 res = make_float4(acc[r][0], acc[r][1], acc[r][2], acc[r][3]);
        if (BIAS) {
            float4 b4 = *(const float4*)(bias + n);
            res.x += b4.x; res.y += b4.y; res.z += b4.z; res.w += b4.w;
        }
        if (ACC) {
            float4 o4 = *(const float4*)&C[(size_t)m*ldc + n];
            res.x += o4.x; res.y += o4.y; res.z += o4.z; res.w += o4.w;
        }
        if (RELU) {
            res.x = fmaxf(res.x, 0.f); res.y = fmaxf(res.y, 0.f);
            res.z = fmaxf(res.z, 0.f); res.w = fmaxf(res.w, 0.f);
        }
        *(float4*)&C[(size_t)m*ldc + n] = res;
    }
}

/* ------------------- beff = Wqq @ bq + bq_mha ---------------------------- */
__global__ void k_beff(const float* md_w, const float* me_w,
                       const float* bqd, const float* bqe,
                       const float* mdb, const float* meb, float* beff)
{
    int l = blockIdx.x, s = blockIdx.y, n = threadIdx.x;
    const float* wqq = (s ? me_w : md_w) + l*384*128;
    const float* bq  = (s ? bqe  : bqd ) + l*128;
    const float* bm  = (s ? meb  : mdb ) + l*384;
    float v = bm[n];
    for (int j = 0; j < 128; j++) v += wqq[n*128 + j]*bq[j];
    beff[(l*2 + s)*128 + n] = v;
}

/* ------------------- cb[row,h] = qh_h . bk_h ----------------------------- */
__global__ void k_cbuf(const float* __restrict__ qh, const float* __restrict__ bk,
                       float* __restrict__ cb)
{
    int idx = blockIdx.x * blockDim.x + threadIdx.x;
    if (idx >= ROWS*4) return;
    int row = idx >> 2, h = idx & 3;
    const float* q = qh + (size_t)row*DIM + h*32;
    const float* b = bk + h*32;
    float s = 0.f;
#pragma unroll
    for (int r = 0; r < 32; r++) s += q[r]*b[r];
    cb[idx] = s;
}

/* ------------------- flash cross-attention over raw segments ------------- */
/* 64 (latent,head) pairs per batch; 4 threads/pair; thread qd owns float4  */
/* chunks c with c%4==qd (bank-conflict-free smem reads).                   */
__global__ void __launch_bounds__(256, 2)
k_attn(const float* __restrict__ kraw, const float* __restrict__ vraw,
       const int* __restrict__ starts, const int* __restrict__ lens,
       const float* __restrict__ qt, const float* __restrict__ cb,
       float* __restrict__ U)
{
    __shared__ __align__(16) float ks[32*DIM];
    __shared__ __align__(16) float vs[32*DIM];
    __shared__ float ps[64*33];
    const float invs = 0.17677669529663687f;  /* 1/sqrt(32) */
    int b = blockIdx.x;
    int t = threadIdx.x;
    int p = t >> 2, qd = t & 3;
    int row = b*NLAT + (p >> 2);
    int h = p & 3;

    const float* qb = qt + (size_t)row*512 + h*128;
    float4 q[8];
#pragma unroll
    for (int c = 0; c < 8; c++) q[c] = *(const float4*)(qb + (c*4 + qd)*4);
    float cbv = cb[row*4 + h] * invs;

    int s0 = starts[b], L = lens[b];
    float4 acc[8];
#pragma unroll
    for (int c = 0; c < 8; c++) acc[c] = make_float4(0.f, 0.f, 0.f, 0.f);
    float m = -1e30f, l = 0.f;

    for (int j0 = 0; j0 < L; j0 += 32) {
        int tc = min(32, L - j0);
        __syncthreads();
#pragma unroll
        for (int u = 0; u < 4; u++) {
            int i = t + u*256;
            int j = i >> 5, c4 = i & 31;
            if (j < tc) {
                const float4* gk = (const float4*)(kraw + (size_t)(s0 + j0 + j)*DIM);
                const float4* gv = (const float4*)(vraw + (size_t)(s0 + j0 + j)*DIM);
                ((float4*)ks)[i] = gk[c4];
                ((float4*)vs)[i] = gv[c4];
            }
        }
        __syncthreads();

        float tmax = -1e30f;
        for (int j = 0; j < tc; j++) {
            const float4* kr = (const float4*)(ks + j*DIM);
            float part = 0.f;
#pragma unroll
            for (int c = 0; c < 8; c++) {
                float4 kk = kr[c*4 + qd];
                part += q[c].x*kk.x + q[c].y*kk.y + q[c].z*kk.z + q[c].w*kk.w;
            }
            part += __shfl_xor_sync(0xffffffffu, part, 1);
            part += __shfl_xor_sync(0xffffffffu, part, 2);
            float sj = part*invs + cbv;
            if (qd == 0) ps[p*33 + j] = sj;
            tmax = fmaxf(tmax, sj);
        }
        __syncwarp();

        float mn = fmaxf(m, tmax);
        float sc = __expf(m - mn);
        l *= sc;
#pragma unroll
        for (int c = 0; c < 8; c++) {
            acc[c].x *= sc; acc[c].y *= sc; acc[c].z *= sc; acc[c].w *= sc;
        }
        m = mn;
        for (int j = 0; j < tc; j++) {
            float a = __expf(ps[p*33 + j] - m);
            l += a;
            const float4* vr = (const float4*)(vs + j*DIM);
#pragma unroll
            for (int c = 0; c < 8; c++) {
                float4 vv = vr[c*4 + qd];
                acc[c].x += a*vv.x; acc[c].y += a*vv.y;
                acc[c].z += a*vv.z; acc[c].w += a*vv.w;
            }
        }
        __syncwarp();
    }

    float inv = (l > 0.f) ? 1.f/l : 0.f;
    float* ub = U + (size_t)row*512 + h*128;
#pragma unroll
    for (int c = 0; c < 8; c++) {
        float4 r = acc[c];
        r.x *= inv; r.y *= inv; r.z *= inv; r.w *= inv;
        *(float4*)(ub + (c*4 + qd)*4) = r;
    }
}

/* ------------------- final head: dot + softplus -------------------------- */
__global__ void k_head2(const float* __restrict__ hh, const float* __restrict__ w2,
                        const float* __restrict__ b2, float* __restrict__ out)
{
    int b = blockIdx.x*8 + (threadIdx.x >> 5);
    int lane = threadIdx.x & 31;
    if (b >= BATCH) return;
    float4 h4 = *(const float4*)(hh + (size_t)b*DIM + lane*4);
    float4 w4 = *(const float4*)(w2 + lane*4);
    float s = h4.x*w4.x + h4.y*w4.y + h4.z*w4.z + h4.w*w4.w;
#pragma unroll
    for (int o = 16; o > 0; o >>= 1) s += __shfl_xor_sync(0xffffffffu, s, o);
    s += b2[0];
    float sp = fmaxf(s, 0.f) + log1pf(__expf(-fabsf(s)));
    if (lane == 0) out[b] = sp;
}

/* ------------------------------------------------------------------------ */
extern "C" void kernel_launch(void* const* d_in, const int* in_sizes, int n_in,
                              void* d_out, int out_size)
{
    const float* drug_k = (const float*)d_in[0];
    const float* drug_v = (const float*)d_in[1];
    const float* enz_k  = (const float*)d_in[2];
    const float* enz_v  = (const float*)d_in[3];
    const int*   drug_b = (const int*)d_in[4];
    const int*   enz_b  = (const int*)d_in[5];
    const float* latents= (const float*)d_in[6];
    const float* wq_d   = (const float*)d_in[7];
    const float* bq_d   = (const float*)d_in[8];
    const float* wq_e   = (const float*)d_in[9];
    const float* bq_e   = (const float*)d_in[10];
    const float* md_w   = (const float*)d_in[11];
    const float* md_b   = (const float*)d_in[12];
    const float* md_ow  = (const float*)d_in[13];
    const float* md_ob  = (const float*)d_in[14];
    const float* me_w   = (const float*)d_in[15];
    const float* me_b   = (const float*)d_in[16];
    const float* me_ow  = (const float*)d_in[17];
    const float* me_ob  = (const float*)d_in[18];
    const float* ln1g   = (const float*)d_in[19];
    const float* ln1b   = (const float*)d_in[20];
    const float* ln2g   = (const float*)d_in[21];
    const float* ln2b   = (const float*)d_in[22];
    const float* fw1    = (const float*)d_in[23];
    const float* fb1    = (const float*)d_in[24];
    const float* fw2    = (const float*)d_in[25];
    const float* fb2    = (const float*)d_in[26];
    const float* hw1    = (const float*)d_in[27];
    const float* hb1    = (const float*)d_in[28];
    const float* hw2    = (const float*)d_in[29];
    const float* hb2    = (const float*)d_in[30];

    int nD = in_sizes[0] / DIM;
    int nE = in_sizes[2] / DIM;

    float *lat, *nl, *qh, *qtb, *cbv, *Ub, *ob, *f1, *hh, *weff, *beff;
    int *sd, *ldp, *se, *lep;
    cudaGetSymbolAddress((void**)&lat,  g_lat);
    cudaGetSymbolAddress((void**)&nl,   g_nl);
    cudaGetSymbolAddress((void**)&qh,   g_qh);
    cudaGetSymbolAddress((void**)&qtb,  g_qt);
    cudaGetSymbolAddress((void**)&cbv,  g_cb);
    cudaGetSymbolAddress((void**)&Ub,   g_U);
    cudaGetSymbolAddress((void**)&ob,   g_o);
    cudaGetSymbolAddress((void**)&f1,   g_f1);
    cudaGetSymbolAddress((void**)&hh,   g_hh);
    cudaGetSymbolAddress((void**)&weff, g_weff);
    cudaGetSymbolAddress((void**)&beff, g_beff);
    cudaGetSymbolAddress((void**)&sd,   g_sd);
    cudaGetSymbolAddress((void**)&ldp,  g_ldn);
    cudaGetSymbolAddress((void**)&se,   g_se);
    cudaGetSymbolAddress((void**)&lep,  g_len);

    k_bounds<<<2, 256>>>(drug_b, nD, 128, sd, ldp);
    k_bounds<<<2, 256>>>(enz_b,  nE, 512, se, lep);
    k_init<<<ROWS*DIM/256, 256>>>(latents, lat);

    /* fold Weff = Wqq @ Wq per (layer, side); beff = Wqq bq + bq_mha */
    k_gemm<128,false,false,false,false><<<dim3(2,1,4), 256>>>(
        md_w, 128, 384*128, wq_d, 128, 128*128, nullptr, 0,
        weff, 128, 2*16384, 128, 128);
    k_gemm<128,false,false,false,false><<<dim3(2,1,4), 256>>>(
        me_w, 128, 384*128, wq_e, 128, 128*128, nullptr, 0,
        weff + 16384, 128, 2*16384, 128, 128);
    k_beff<<<dim3(4,2), 128>>>(md_w, me_w, bq_d, bq_e, md_b, me_b, beff);

    for (int l = 0; l < 4; l++) {
        k_ln<<<1024, 256>>>(lat, ln1g + l*128, ln1b + l*128, nl, ROWS);
        for (int s = 0; s < 2; s++) {
            const float* mw  = s ? me_w  : md_w;
            const float* mb  = s ? me_b  : md_b;
            const float* ow  = s ? me_ow : md_ow;
            const float* obv = s ? me_ob : md_ob;
            const float* kr  = s ? enz_k : drug_k;
            const float* vr  = s ? enz_v : drug_v;
            const int*   st  = s ? se : sd;
            const int*   ln  = s ? lep : ldp;
            int pi = l*2 + s;

            /* qh = nl @ Weff^T + beff */
            k_gemm<128,true,true,false,false><<<dim3(128,1,1), 256>>>(
                nl, 128, 0, weff + pi*16384, 128, 0, beff + pi*128, 0,
                qh, 128, 0, ROWS, 128);
            /* qt[row,h,:] = Wk_h^T qh_h  (batched over heads, K=32) */
            k_gemm<128,false,false,false,false><<<dim3(128,1,4), 256>>>(
                qh, 128, 32, mw + l*384*128 + 128*128, 128, 32*128, nullptr, 0,
                qtb, 512, 128, ROWS, 32);
            k_cbuf<<<128, 256>>>(qh, mb + l*384 + 128, cbv);
            k_attn<<<512, 256>>>(kr, vr, st, ln, qtb, cbv, Ub);
            /* o[.,h*32:] = Wv_h u_h + bv_h  (batched over heads, BN=32) */
            k_gemm<32,true,true,false,false><<<dim3(128,1,4), 256>>>(
                Ub, 512, 128, mw + l*384*128 + 256*128, 128, 32*128,
                mb + l*384 + 256, 32, ob, 128, 32, ROWS, 128);
            /* lat += o @ ow^T + ob */
            k_gemm<128,true,true,true,false><<<dim3(128,1,1), 256>>>(
                ob, 128, 0, ow + l*16384, 128, 0, obv + l*128, 0,
                lat, 128, 0, ROWS, 128);
        }
        /* FFN */
        k_ln<<<1024, 256>>>(lat, ln2g + l*128, ln2b + l*128, nl, ROWS);
        k_gemm<128,true,true,false,true><<<dim3(128,2,1), 256>>>(
            nl, 128, 0, fw1 + l*256*128, 128, 0, fb1 + l*256, 0,
            f1, 256, 0, ROWS, 128);
        k_gemm<128,true,true,true,false><<<dim3(128,1,1), 256>>>(
            f1, 256, 0, fw2 + l*128*256, 256, 0, fb2 + l*128, 0,
            lat, 128, 0, ROWS, 256);
    }

    /* head: hh = relu(flat @ hw1^T + hb1); out = softplus(hh @ hw2^T + hb2) */
    k_gemm<128,true,true,false,true><<<dim3(8,1,1), 256>>>(
        lat, 2048, 0, hw1, 2048, 0, hb1, 0, hh, 128, 0, BATCH, 2048);
    k_head2<<<64, 256>>>(hh, hw2, hb2, (float*)d_out);
}

// round 11
// speedup vs baseline: 1.0545x; 1.0545x over previous
#include <cuda_runtime.h>
#include <math.h>

#define BATCH 512
#define NLAT  16
#define DIM   128
#define ROWS  (BATCH*NLAT)   /* 8192 */

/* ------------------- scratch (no allocations allowed) ------------------- */
__device__ float g_lat [ROWS*DIM];
__device__ float g_nl  [ROWS*DIM];
__device__ float g_qh  [ROWS*DIM];
__device__ float g_qt  [ROWS*512];
__device__ float g_cb  [ROWS*4];
__device__ float g_U   [ROWS*512];
__device__ float g_o   [ROWS*DIM];
__device__ float g_f1  [ROWS*256];
__device__ float g_hh  [BATCH*DIM];
__device__ float g_weff[8*DIM*DIM];
__device__ float g_beff[8*DIM];
__device__ int   g_sd[BATCH], g_ldn[BATCH], g_se[BATCH], g_len[BATCH];

/* ------------------- segment bounds from sorted batch ids --------------- */
__global__ void k_bounds(const int* __restrict__ batch, int n, int maxlen,
                         int* __restrict__ start, int* __restrict__ len)
{
    int b = blockIdx.x * blockDim.x + threadIdx.x;
    if (b >= BATCH) return;
    int lo = 0, hi = n;
    while (lo < hi) { int mid = (lo + hi) >> 1; if (batch[mid] < b) lo = mid + 1; else hi = mid; }
    int s = lo;
    lo = s; hi = n;
    while (lo < hi) { int mid = (lo + hi) >> 1; if (batch[mid] < b + 1) lo = mid + 1; else hi = mid; }
    int L = lo - s;
    if (L > maxlen) L = maxlen;   /* JAX OOB scatter drops tokens beyond maxlen */
    start[b] = s; len[b] = L;
}

__global__ void k_init(const float* __restrict__ latents, float* __restrict__ lat)
{
    int idx = blockIdx.x * blockDim.x + threadIdx.x;
    if (idx < ROWS*DIM) lat[idx] = latents[idx & (NLAT*DIM - 1)];
}

/* ------------------- LayerNorm, one warp per 128-dim row ---------------- */
__global__ void __launch_bounds__(256) k_ln(const float* __restrict__ x,
                                            const float* __restrict__ g,
                                            const float* __restrict__ bt,
                                            float* __restrict__ y, int M)
{
    int row  = blockIdx.x * 8 + (threadIdx.x >> 5);
    int lane = threadIdx.x & 31;
    if (row >= M) return;
    float4 v = *(const float4*)(x + (size_t)row*DIM + lane*4);
    float s = v.x + v.y + v.z + v.w;
#pragma unroll
    for (int o = 16; o > 0; o >>= 1) s += __shfl_xor_sync(0xffffffffu, s, o);
    float m = s * (1.0f/128.0f);
    float d0 = v.x-m, d1 = v.y-m, d2 = v.z-m, d3 = v.w-m;
    float q = d0*d0 + d1*d1 + d2*d2 + d3*d3;
#pragma unroll
    for (int o = 16; o > 0; o >>= 1) q += __shfl_xor_sync(0xffffffffu, q, o);
    float inv = rsqrtf(q * (1.0f/128.0f) + 1e-5f);
    float4 gg = *(const float4*)(g  + lane*4);
    float4 bb = *(const float4*)(bt + lane*4);
    float4 o4;
    o4.x = d0*inv*gg.x + bb.x;  o4.y = d1*inv*gg.y + bb.y;
    o4.z = d2*inv*gg.z + bb.z;  o4.w = d3*inv*gg.w + bb.w;
    *(float4*)(y + (size_t)row*DIM + lane*4) = o4;
}

/* ------------------- generic fp32 GEMM ---------------------------------- */
/* C = act( A[M,K] x op(W) + bias (+C) ).  TRANSW: W stored [N,K].          */
/* blockIdx.z applies batched offsets.  BM=64, BK=32, BN in {32,128}.       */
template<int BN, bool TRANSW, bool BIAS, bool ACC, bool RELU>
__global__ void __launch_bounds__(256)
k_gemm(const float* __restrict__ A, int lda, int aSz,
       const float* __restrict__ W, int ldw, int wSz,
       const float* __restrict__ Bv, int bSz,
       float* __restrict__ C, int ldc, int cSz,
       int M, int K)
{
    constexpr int BM = 64, BK = 32;
    constexpr int TX = BN/4;
    constexpr int TY = 256/TX;
    constexpr int RT = BM/TY;
    constexpr int NA = BM*BK/256;
    constexpr int NW = BN*BK/256;
    __shared__ __align__(16) float As[BK][BM+4];
    __shared__ __align__(16) float Ws[BK][BN+4];

    A += (size_t)blockIdx.z * aSz;
    W += (size_t)blockIdx.z * wSz;
    C += (size_t)blockIdx.z * cSz;
    const float* bias = nullptr;
    if (BIAS) bias = Bv + (size_t)blockIdx.z * bSz;

    int t = threadIdx.x;
    int tx = t % TX, ty = t / TX;
    int mBase = blockIdx.x * BM, nBase = blockIdx.y * BN;

    float acc[RT][4];
#pragma unroll
    for (int r = 0; r < RT; r++) { acc[r][0]=0.f; acc[r][1]=0.f; acc[r][2]=0.f; acc[r][3]=0.f; }

    for (int k0 = 0; k0 < K; k0 += BK) {
#pragma unroll
        for (int u = 0; u < NA; u++) {
            int i = t + u*256;
            int r = i >> 5, c = i & 31;
            As[c][r] = A[(size_t)(mBase + r) * lda + k0 + c];
        }
        if (TRANSW) {
#pragma unroll
            for (int u = 0; u < NW; u++) {
                int i = t + u*256;
                int n = i >> 5, c = i & 31;
                Ws[c][n] = W[(size_t)(nBase + n) * ldw + k0 + c];
            }
        } else {
#pragma unroll
            for (int u = 0; u < NW; u++) {
                int i = t + u*256;
                int c = i / BN, n = i % BN;
                Ws[c][n] = W[(size_t)(k0 + c) * ldw + nBase + n];
            }
        }
        __syncthreads();
#pragma unroll
        for (int kk = 0; kk < BK; kk++) {
            float av[RT];
#pragma unroll
            for (int r = 0; r < RT; r++) av[r] = As[kk][ty*RT + r];
            float4 b4 = *(const float4*)&Ws[kk][tx*4];
#pragma unroll
            for (int r = 0; r < RT; r++) {
                acc[r][0] += av[r]*b4.x; acc[r][1] += av[r]*b4.y;
                acc[r][2] += av[r]*b4.z; acc[r][3] += av[r]*b4.w;
            }
        }
        __syncthreads();
    }

#pragma unroll
    for (int r = 0; r < RT; r++) {
        int m = mBase + ty*RT + r;
        int n = nBase + tx*4;
        float4 res = make_float4(acc[r][0], acc[r][1], acc[r][2], acc[r][3]);
        if (BIAS) {
            float4 b4 = *(const float4*)(bias + n);
            res.x += b4.x; res.y += b4.y; res.z += b4.z; res.w += b4.w;
        }
        if (ACC) {
            float4 o4 = *(const float4*)&C[(size_t)m*ldc + n];
            res.x += o4.x; res.y += o4.y; res.z += o4.z; res.w += o4.w;
        }
        if (RELU) {
            res.x = fmaxf(res.x, 0.f); res.y = fmaxf(res.y, 0.f);
            res.z = fmaxf(res.z, 0.f); res.w = fmaxf(res.w, 0.f);
        }
        *(float4*)&C[(size_t)m*ldc + n] = res;
    }
}

/* ------------------- beff = Wqq @ bq + bq_mha ---------------------------- */
__global__ void k_beff(const float* md_w, const float* me_w,
                       const float* bqd, const float* bqe,
                       const float* mdb, const float* meb, float* beff)
{
    int l = blockIdx.x, s = blockIdx.y, n = threadIdx.x;
    const float* wqq = (s ? me_w : md_w) + l*384*128;
    const float* bq  = (s ? bqe  : bqd ) + l*128;
    const float* bm  = (s ? meb  : mdb ) + l*384;
    float v = bm[n];
    for (int j = 0; j < 128; j++) v += wqq[n*128 + j]*bq[j];
    beff[(l*2 + s)*128 + n] = v;
}

/* ------------------- cb[row,h] = qh_h . bk_h ----------------------------- */
__global__ void k_cbuf(const float* __restrict__ qh, const float* __restrict__ bk,
                       float* __restrict__ cb)
{
    int idx = blockIdx.x * blockDim.x + threadIdx.x;
    if (idx >= ROWS*4) return;
    int row = idx >> 2, h = idx & 3;
    const float* q = qh + (size_t)row*DIM + h*32;
    const float* b = bk + h*32;
    float s = 0.f;
#pragma unroll
    for (int r = 0; r < 32; r++) s += q[r]*b[r];
    cb[idx] = s;
}

/* ------------------- flash cross-attention over raw segments ------------- */
/* 64 (latent,head) pairs per batch; 4 threads/pair; thread qd owns float4  */
/* chunks c with c%4==qd (bank-conflict-free smem reads).                   */
__global__ void __launch_bounds__(256, 2)
k_attn(const float* __restrict__ kraw, const float* __restrict__ vraw,
       const int* __restrict__ starts, const int* __restrict__ lens,
       const float* __restrict__ qt, const float* __restrict__ cb,
       float* __restrict__ U)
{
    __shared__ __align__(16) float ks[32*DIM];
    __shared__ __align__(16) float vs[32*DIM];
    __shared__ float ps[64*33];
    const float invs = 0.17677669529663687f;  /* 1/sqrt(32) */
    int b = blockIdx.x;
    int t = threadIdx.x;
    int p = t >> 2, qd = t & 3;
    int row = b*NLAT + (p >> 2);
    int h = p & 3;

    const float* qb = qt + (size_t)row*512 + h*128;
    float4 q[8];
#pragma unroll
    for (int c = 0; c < 8; c++) q[c] = *(const float4*)(qb + (c*4 + qd)*4);
    float cbv = cb[row*4 + h] * invs;

    int s0 = starts[b], L = lens[b];
    float4 acc[8];
#pragma unroll
    for (int c = 0; c < 8; c++) acc[c] = make_float4(0.f, 0.f, 0.f, 0.f);
    float m = -1e30f, l = 0.f;

    for (int j0 = 0; j0 < L; j0 += 32) {
        int tc = min(32, L - j0);
        __syncthreads();
#pragma unroll
        for (int u = 0; u < 4; u++) {
            int i = t + u*256;
            int j = i >> 5, c4 = i & 31;
            if (j < tc) {
                const float4* gk = (const float4*)(kraw + (size_t)(s0 + j0 + j)*DIM);
                const float4* gv = (const float4*)(vraw + (size_t)(s0 + j0 + j)*DIM);
                ((float4*)ks)[i] = gk[c4];
                ((float4*)vs)[i] = gv[c4];
            }
        }
        __syncthreads();

        float tmax = -1e30f;
        for (int j = 0; j < tc; j++) {
            const float4* kr = (const float4*)(ks + j*DIM);
            float part = 0.f;
#pragma unroll
            for (int c = 0; c < 8; c++) {
                float4 kk = kr[c*4 + qd];
                part += q[c].x*kk.x + q[c].y*kk.y + q[c].z*kk.z + q[c].w*kk.w;
            }
            part += __shfl_xor_sync(0xffffffffu, part, 1);
            part += __shfl_xor_sync(0xffffffffu, part, 2);
            float sj = part*invs + cbv;
            if (qd == 0) ps[p*33 + j] = sj;
            tmax = fmaxf(tmax, sj);
        }
        __syncwarp();

        float mn = fmaxf(m, tmax);
        float sc = __expf(m - mn);
        l *= sc;
#pragma unroll
        for (int c = 0; c < 8; c++) {
            acc[c].x *= sc; acc[c].y *= sc; acc[c].z *= sc; acc[c].w *= sc;
        }
        m = mn;
        for (int j = 0; j < tc; j++) {
            float a = __expf(ps[p*33 + j] - m);
            l += a;
            const float4* vr = (const float4*)(vs + j*DIM);
#pragma unroll
            for (int c = 0; c < 8; c++) {
                float4 vv = vr[c*4 + qd];
                acc[c].x += a*vv.x; acc[c].y += a*vv.y;
                acc[c].z += a*vv.z; acc[c].w += a*vv.w;
            }
        }
        __syncwarp();
    }

    float inv = (l > 0.f) ? 1.f/l : 0.f;
    float* ub = U + (size_t)row*512 + h*128;
#pragma unroll
    for (int c = 0; c < 8; c++) {
        float4 r = acc[c];
        r.x *= inv; r.y *= inv; r.z *= inv; r.w *= inv;
        *(float4*)(ub + (c*4 + qd)*4) = r;
    }
}

/* ------------------- final head: dot + softplus -------------------------- */
__global__ void k_head2(const float* __restrict__ hh, const float* __restrict__ w2,
                        const float* __restrict__ b2, float* __restrict__ out)
{
    int b = blockIdx.x*8 + (threadIdx.x >> 5);
    int lane = threadIdx.x & 31;
    if (b >= BATCH) return;
    float4 h4 = *(const float4*)(hh + (size_t)b*DIM + lane*4);
    float4 w4 = *(const float4*)(w2 + lane*4);
    float s = h4.x*w4.x + h4.y*w4.y + h4.z*w4.z + h4.w*w4.w;
#pragma unroll
    for (int o = 16; o > 0; o >>= 1) s += __shfl_xor_sync(0xffffffffu, s, o);
    s += b2[0];
    float sp = fmaxf(s, 0.f) + log1pf(__expf(-fabsf(s)));
    if (lane == 0) out[b] = sp;
}

/* ------------------------------------------------------------------------ */
extern "C" void kernel_launch(void* const* d_in, const int* in_sizes, int n_in,
                              void* d_out, int out_size)
{
    const float* drug_k = (const float*)d_in[0];
    const float* drug_v = (const float*)d_in[1];
    const float* enz_k  = (const float*)d_in[2];
    const float* enz_v  = (const float*)d_in[3];
    const int*   drug_b = (const int*)d_in[4];
    const int*   enz_b  = (const int*)d_in[5];
    const float* latents= (const float*)d_in[6];
    const float* wq_d   = (const float*)d_in[7];
    const float* bq_d   = (const float*)d_in[8];
    const float* wq_e   = (const float*)d_in[9];
    const float* bq_e   = (const float*)d_in[10];
    const float* md_w   = (const float*)d_in[11];
    const float* md_b   = (const float*)d_in[12];
    const float* md_ow  = (const float*)d_in[13];
    const float* md_ob  = (const float*)d_in[14];
    const float* me_w   = (const float*)d_in[15];
    const float* me_b   = (const float*)d_in[16];
    const float* me_ow  = (const float*)d_in[17];
    const float* me_ob  = (const float*)d_in[18];
    const float* ln1g   = (const float*)d_in[19];
    const float* ln1b   = (const float*)d_in[20];
    const float* ln2g   = (const float*)d_in[21];
    const float* ln2b   = (const float*)d_in[22];
    const float* fw1    = (const float*)d_in[23];
    const float* fb1    = (const float*)d_in[24];
    const float* fw2    = (const float*)d_in[25];
    const float* fb2    = (const float*)d_in[26];
    const float* hw1    = (const float*)d_in[27];
    const float* hb1    = (const float*)d_in[28];
    const float* hw2    = (const float*)d_in[29];
    const float* hb2    = (const float*)d_in[30];

    int nD = in_sizes[0] / DIM;
    int nE = in_sizes[2] / DIM;

    float *lat, *nl, *qh, *qtb, *cbv, *Ub, *ob, *f1, *hh, *weff, *beff;
    int *sd, *ldp, *se, *lep;
    cudaGetSymbolAddress((void**)&lat,  g_lat);
    cudaGetSymbolAddress((void**)&nl,   g_nl);
    cudaGetSymbolAddress((void**)&qh,   g_qh);
    cudaGetSymbolAddress((void**)&qtb,  g_qt);
    cudaGetSymbolAddress((void**)&cbv,  g_cb);
    cudaGetSymbolAddress((void**)&Ub,   g_U);
    cudaGetSymbolAddress((void**)&ob,   g_o);
    cudaGetSymbolAddress((void**)&f1,   g_f1);
    cudaGetSymbolAddress((void**)&hh,   g_hh);
    cudaGetSymbolAddress((void**)&weff, g_weff);
    cudaGetSymbolAddress((void**)&beff, g_beff);
    cudaGetSymbolAddress((void**)&sd,   g_sd);
    cudaGetSymbolAddress((void**)&ldp,  g_ldn);
    cudaGetSymbolAddress((void**)&se,   g_se);
    cudaGetSymbolAddress((void**)&lep,  g_len);

    k_bounds<<<2, 256>>>(drug_b, nD, 128, sd, ldp);
    k_bounds<<<2, 256>>>(enz_b,  nE, 512, se, lep);
    k_init<<<ROWS*DIM/256, 256>>>(latents, lat);

    /* fold Weff = Wqq @ Wq per (layer, side); beff = Wqq bq + bq_mha */
    k_gemm<128,false,false,false,false><<<dim3(2,1,4), 256>>>(
        md_w, 128, 384*128, wq_d, 128, 128*128, nullptr, 0,
        weff, 128, 2*16384, 128, 128);
    k_gemm<128,false,false,false,false><<<dim3(2,1,4), 256>>>(
        me_w, 128, 384*128, wq_e, 128, 128*128, nullptr, 0,
        weff + 16384, 128, 2*16384, 128, 128);
    k_beff<<<dim3(4,2), 128>>>(md_w, me_w, bq_d, bq_e, md_b, me_b, beff);

    for (int l = 0; l < 4; l++) {
        k_ln<<<1024, 256>>>(lat, ln1g + l*128, ln1b + l*128, nl, ROWS);
        for (int s = 0; s < 2; s++) {
            const float* mw  = s ? me_w  : md_w;
            const float* mb  = s ? me_b  : md_b;
            const float* ow  = s ? me_ow : md_ow;
            const float* obv = s ? me_ob : md_ob;
            const float* kr  = s ? enz_k : drug_k;
            const float* vr  = s ? enz_v : drug_v;
            const int*   st  = s ? se : sd;
            const int*   ln  = s ? lep : ldp;
            int pi = l*2 + s;

            /* qh = nl @ Weff^T + beff */
            k_gemm<128,true,true,false,false><<<dim3(128,1,1), 256>>>(
                nl, 128, 0, weff + pi*16384, 128, 0, beff + pi*128, 0,
                qh, 128, 0, ROWS, 128);
            /* qt[row,h,:] = Wk_h^T qh_h  (batched over heads, K=32) */
            k_gemm<128,false,false,false,false><<<dim3(128,1,4), 256>>>(
                qh, 128, 32, mw + l*384*128 + 128*128, 128, 32*128, nullptr, 0,
                qtb, 512, 128, ROWS, 32);
            k_cbuf<<<128, 256>>>(qh, mb + l*384 + 128, cbv);
            k_attn<<<512, 256>>>(kr, vr, st, ln, qtb, cbv, Ub);
            /* o[.,h*32:] = Wv_h u_h + bv_h  (batched over heads, BN=32) */
            k_gemm<32,true,true,false,false><<<dim3(128,1,4), 256>>>(
                Ub, 512, 128, mw + l*384*128 + 256*128, 128, 32*128,
                mb + l*384 + 256, 32, ob, 128, 32, ROWS, 128);
            /* lat += o @ ow^T + ob */
            k_gemm<128,true,true,true,false><<<dim3(128,1,1), 256>>>(
                ob, 128, 0, ow + l*16384, 128, 0, obv + l*128, 0,
                lat, 128, 0, ROWS, 128);
        }
        /* FFN */
        k_ln<<<1024, 256>>>(lat, ln2g + l*128, ln2b + l*128, nl, ROWS);
        k_gemm<128,true,true,false,true><<<dim3(128,2,1), 256>>>(
            nl, 128, 0, fw1 + l*256*128, 128, 0, fb1 + l*256, 0,
            f1, 256, 0, ROWS, 128);
        k_gemm<128,true,true,true,false><<<dim3(128,1,1), 256>>>(
            f1, 256, 0, fw2 + l*128*256, 256, 0, fb2 + l*128, 0,
            lat, 128, 0, ROWS, 256);
    }

    /* head: hh = relu(flat @ hw1^T + hb1); out = softplus(hh @ hw2^T + hb2) */
    k_gemm<128,true,true,false,true><<<dim3(8,1,1), 256>>>(
        lat, 2048, 0, hw1, 2048, 0, hb1, 0, hh, 128, 0, BATCH, 2048);
    k_head2<<<64, 256>>>(hh, hw2, hb2, (float*)d_out);
}

// round 14
// speedup vs baseline: 1.1579x; 1.0980x over previous
#include <cuda_runtime.h>
#include <math.h>

#define BATCH 512
#define NLAT  16
#define DIM   128
#define ROWS  (BATCH*NLAT)   /* 8192 */

typedef unsigned long long u64;

/* packed fp32x2 ops (sm_100+): per-lane IEEE FMA at 2x FFMA rate */
#define FMA2(d,a,b,c) asm("fma.rn.f32x2 %0, %1, %2, %3;" : "=l"(d) : "l"(a), "l"(b), "l"(c))
#define MUL2(d,a,b)   asm("mul.rn.f32x2 %0, %1, %2;"     : "=l"(d) : "l"(a), "l"(b))
#define ADD2(d,a,b)   asm("add.rn.f32x2 %0, %1, %2;"     : "=l"(d) : "l"(a), "l"(b))
#define PACK2(d,lo,hi) asm("mov.b64 %0, {%1, %2};" : "=l"(d) : "r"(lo), "r"(hi))
#define UNPK2(lo,hi,x) asm("mov.b64 {%0, %1}, %2;" : "=r"(lo), "=r"(hi) : "l"(x))

/* ------------------- scratch (no allocations allowed) ------------------- */
__device__ float g_lat [ROWS*DIM];
__device__ float g_nl  [ROWS*DIM];
__device__ float g_qh  [ROWS*DIM];
__device__ float g_qt  [ROWS*512];
__device__ float g_cb  [ROWS*4];
__device__ float g_U   [ROWS*512];     /* also reused as head split-K partials */
__device__ float g_o   [ROWS*DIM];
__device__ float g_f1  [ROWS*256];
__device__ float g_hh  [BATCH*DIM];
__device__ float g_weff[8*DIM*DIM];
__device__ float g_beff[8*DIM];
__device__ int   g_sd[BATCH], g_ldn[BATCH], g_se[BATCH], g_len[BATCH];

/* ------------------- segment bounds from sorted batch ids --------------- */
__global__ void k_bounds(const int* __restrict__ batch, int n, int maxlen,
                         int* __restrict__ start, int* __restrict__ len)
{
    int b = blockIdx.x * blockDim.x + threadIdx.x;
    if (b >= BATCH) return;
    int lo = 0, hi = n;
    while (lo < hi) { int mid = (lo + hi) >> 1; if (batch[mid] < b) lo = mid + 1; else hi = mid; }
    int s = lo;
    lo = s; hi = n;
    while (lo < hi) { int mid = (lo + hi) >> 1; if (batch[mid] < b + 1) lo = mid + 1; else hi = mid; }
    int L = lo - s;
    if (L > maxlen) L = maxlen;   /* JAX OOB scatter drops tokens beyond maxlen */
    start[b] = s; len[b] = L;
}

__global__ void k_init(const float* __restrict__ latents, float* __restrict__ lat)
{
    int idx = blockIdx.x * blockDim.x + threadIdx.x;
    if (idx < ROWS*DIM) lat[idx] = latents[idx & (NLAT*DIM - 1)];
}

/* ------------------- LayerNorm, one warp per 128-dim row ---------------- */
__global__ void __launch_bounds__(256) k_ln(const float* __restrict__ x,
                                            const float* __restrict__ g,
                                            const float* __restrict__ bt,
                                            float* __restrict__ y, int M)
{
    int row  = blockIdx.x * 8 + (threadIdx.x >> 5);
    int lane = threadIdx.x & 31;
    if (row >= M) return;
    float4 v = *(const float4*)(x + (size_t)row*DIM + lane*4);
    float s = v.x + v.y + v.z + v.w;
#pragma unroll
    for (int o = 16; o > 0; o >>= 1) s += __shfl_xor_sync(0xffffffffu, s, o);
    float m = s * (1.0f/128.0f);
    float d0 = v.x-m, d1 = v.y-m, d2 = v.z-m, d3 = v.w-m;
    float q = d0*d0 + d1*d1 + d2*d2 + d3*d3;
#pragma unroll
    for (int o = 16; o > 0; o >>= 1) q += __shfl_xor_sync(0xffffffffu, q, o);
    float inv = rsqrtf(q * (1.0f/128.0f) + 1e-5f);
    float4 gg = *(const float4*)(g  + lane*4);
    float4 bb = *(const float4*)(bt + lane*4);
    float4 o4;
    o4.x = d0*inv*gg.x + bb.x;  o4.y = d1*inv*gg.y + bb.y;
    o4.z = d2*inv*gg.z + bb.z;  o4.w = d3*inv*gg.w + bb.w;
    *(float4*)(y + (size_t)row*DIM + lane*4) = o4;
}

/* ------------------- generic fp32 GEMM, f32x2 inner --------------------- */
/* C = act( A[M,K] x op(W) + bias (+C) ).  TRANSW: W stored [N,K].          */
/* blockIdx.z applies batched offsets.  acc packed over m-pairs (f32x2).    */
template<int BM, int BN, bool TRANSW, bool BIAS, bool ACCUM, bool RELU>
__global__ void __launch_bounds__(256)
k_gemm(const float* __restrict__ A, int lda, int aSz,
       const float* __restrict__ W, int ldw, int wSz,
       const float* __restrict__ Bv, int bSz,
       float* __restrict__ C, int ldc, int cSz,
       int M, int K)
{
    constexpr int BK = 32;
    constexpr int TX = BN/4;
    constexpr int TY = 256/TX;
    constexpr int RT = BM/TY;
    constexpr int RP = RT/2;
    static_assert(RT >= 2 && (RT & 1) == 0, "RT must be even");
    constexpr int NA = BM*BK/256;
    constexpr int NW = BN*BK/256;
    __shared__ __align__(16) float As[BK][BM+4];
    __shared__ __align__(16) float Ws[BK][BN+4];

    A += (size_t)blockIdx.z * aSz;
    W += (size_t)blockIdx.z * wSz;
    C += (size_t)blockIdx.z * cSz;
    const float* bias = nullptr;
    if (BIAS) bias = Bv + (size_t)blockIdx.z * bSz;

    int t = threadIdx.x;
    int tx = t % TX, ty = t / TX;
    int mBase = blockIdx.x * BM, nBase = blockIdx.y * BN;

    u64 acc[RP][4];
#pragma unroll
    for (int i = 0; i < RP; i++) { acc[i][0]=0ULL; acc[i][1]=0ULL; acc[i][2]=0ULL; acc[i][3]=0ULL; }

    for (int k0 = 0; k0 < K; k0 += BK) {
#pragma unroll
        for (int u = 0; u < NA; u++) {
            int i = t + u*256;
            int r = i >> 5, c = i & 31;
            As[c][r] = A[(size_t)(mBase + r) * lda + k0 + c];
        }
        if (TRANSW) {
#pragma unroll
            for (int u = 0; u < NW; u++) {
                int i = t + u*256;
                int n = i >> 5, c = i & 31;
                Ws[c][n] = W[(size_t)(nBase + n) * ldw + k0 + c];
            }
        } else {
#pragma unroll
            for (int u = 0; u < NW; u++) {
                int i = t + u*256;
                int c = i / BN, n = i % BN;
                Ws[c][n] = W[(size_t)(k0 + c) * ldw + nBase + n];
            }
        }
        __syncthreads();
#pragma unroll
        for (int kk = 0; kk < BK; kk++) {
            float4 b4 = *(const float4*)&Ws[kk][tx*4];
            u64 bp0, bp1, bp2, bp3;
            PACK2(bp0, __float_as_uint(b4.x), __float_as_uint(b4.x));
            PACK2(bp1, __float_as_uint(b4.y), __float_as_uint(b4.y));
            PACK2(bp2, __float_as_uint(b4.z), __float_as_uint(b4.z));
            PACK2(bp3, __float_as_uint(b4.w), __float_as_uint(b4.w));
#pragma unroll
            for (int i = 0; i < RP; i++) {
                u64 ap = *(const u64*)&As[kk][ty*RT + 2*i];
                FMA2(acc[i][0], ap, bp0, acc[i][0]);
                FMA2(acc[i][1], ap, bp1, acc[i][1]);
                FMA2(acc[i][2], ap, bp2, acc[i][2]);
                FMA2(acc[i][3], ap, bp3, acc[i][3]);
            }
        }
        __syncthreads();
    }

#pragma unroll
    for (int i = 0; i < RP; i++) {
        int m0 = mBase + ty*RT + 2*i;
        int n  = nBase + tx*4;
        float r0[4], r1[4];
#pragma unroll
        for (int c = 0; c < 4; c++) {
            unsigned lo, hi;
            UNPK2(lo, hi, acc[i][c]);
            r0[c] = __uint_as_float(lo);
            r1[c] = __uint_as_float(hi);
        }
        if (BIAS) {
            float4 b4 = *(const float4*)(bias + n);
            r0[0]+=b4.x; r0[1]+=b4.y; r0[2]+=b4.z; r0[3]+=b4.w;
            r1[0]+=b4.x; r1[1]+=b4.y; r1[2]+=b4.z; r1[3]+=b4.w;
        }
        if (ACCUM) {
            float4 c0 = *(const float4*)&C[(size_t)m0*ldc + n];
            float4 c1 = *(const float4*)&C[(size_t)(m0+1)*ldc + n];
            r0[0]+=c0.x; r0[1]+=c0.y; r0[2]+=c0.z; r0[3]+=c0.w;
            r1[0]+=c1.x; r1[1]+=c1.y; r1[2]+=c1.z; r1[3]+=c1.w;
        }
        if (RELU) {
#pragma unroll
            for (int c = 0; c < 4; c++) { r0[c]=fmaxf(r0[c],0.f); r1[c]=fmaxf(r1[c],0.f); }
        }
        *(float4*)&C[(size_t)m0*ldc + n]     = make_float4(r0[0],r0[1],r0[2],r0[3]);
        *(float4*)&C[(size_t)(m0+1)*ldc + n] = make_float4(r1[0],r1[1],r1[2],r1[3]);
    }
}

/* ------------------- beff = Wqq @ bq + bq_mha ---------------------------- */
__global__ void k_beff(const float* md_w, const float* me_w,
                       const float* bqd, const float* bqe,
                       const float* mdb, const float* meb, float* beff)
{
    int l = blockIdx.x, s = blockIdx.y, n = threadIdx.x;
    const float* wqq = (s ? me_w : md_w) + l*384*128;
    const float* bq  = (s ? bqe  : bqd ) + l*128;
    const float* bm  = (s ? meb  : mdb ) + l*384;
    float v = bm[n];
    for (int j = 0; j < 128; j++) v += wqq[n*128 + j]*bq[j];
    beff[(l*2 + s)*128 + n] = v;
}

/* ------------------- cb[row,h] = qh_h . bk_h ----------------------------- */
__global__ void k_cbuf(const float* __restrict__ qh, const float* __restrict__ bk,
                       float* __restrict__ cb)
{
    int idx = blockIdx.x * blockDim.x + threadIdx.x;
    if (idx >= ROWS*4) return;
    int row = idx >> 2, h = idx & 3;
    const float* q = qh + (size_t)row*DIM + h*32;
    const float* b = bk + h*32;
    float s = 0.f;
#pragma unroll
    for (int r = 0; r < 32; r++) s += q[r]*b[r];
    cb[idx] = s;
}

/* ------------------- flash cross-attention over raw segments ------------- */
/* 64 (latent,head) pairs per batch; 4 threads/pair; packed f32x2 math.     */
__global__ void __launch_bounds__(256, 2)
k_attn(const float* __restrict__ kraw, const float* __restrict__ vraw,
       const int* __restrict__ starts, const int* __restrict__ lens,
       const float* __restrict__ qt, const float* __restrict__ cb,
       float* __restrict__ U)
{
    __shared__ __align__(16) float ks[32*DIM];
    __shared__ __align__(16) float vs[32*DIM];
    __shared__ float ps[64*33];
    const float invs = 0.17677669529663687f;  /* 1/sqrt(32) */
    int b = blockIdx.x;
    int t = threadIdx.x;
    int p = t >> 2, qd = t & 3;
    int row = b*NLAT + (p >> 2);
    int h = p & 3;

    const float* qb = qt + (size_t)row*512 + h*128;
    u64 qA[8], qB[8];
#pragma unroll
    for (int c = 0; c < 8; c++) {
        ulonglong2 qq = *(const ulonglong2*)(qb + (c*4 + qd)*4);
        qA[c] = qq.x; qB[c] = qq.y;
    }
    float cbv = cb[row*4 + h] * invs;

    int s0 = starts[b], L = lens[b];
    u64 accA[8], accB[8];
#pragma unroll
    for (int c = 0; c < 8; c++) { accA[c] = 0ULL; accB[c] = 0ULL; }
    float m = -1e30f, l = 0.f;

    for (int j0 = 0; j0 < L; j0 += 32) {
        int tc = min(32, L - j0);
        __syncthreads();
#pragma unroll
        for (int u = 0; u < 4; u++) {
            int i = t + u*256;
            int j = i >> 5, c4 = i & 31;
            if (j < tc) {
                const float4* gk = (const float4*)(kraw + (size_t)(s0 + j0 + j)*DIM);
                const float4* gv = (const float4*)(vraw + (size_t)(s0 + j0 + j)*DIM);
                ((float4*)ks)[i] = gk[c4];
                ((float4*)vs)[i] = gv[c4];
            }
        }
        __syncthreads();

        /* scores */
        float tmax = -1e30f;
#pragma unroll 2
        for (int j = 0; j < tc; j++) {
            const ulonglong2* kr = (const ulonglong2*)(ks + j*DIM);
            u64 pa = 0ULL, pb = 0ULL;
#pragma unroll
            for (int c = 0; c < 8; c++) {
                ulonglong2 kk = kr[c*4 + qd];
                FMA2(pa, qA[c], kk.x, pa);
                FMA2(pb, qB[c], kk.y, pb);
            }
            u64 pc; ADD2(pc, pa, pb);
            unsigned lo, hi; UNPK2(lo, hi, pc);
            float part = __uint_as_float(lo) + __uint_as_float(hi);
            part += __shfl_xor_sync(0xffffffffu, part, 1);
            part += __shfl_xor_sync(0xffffffffu, part, 2);
            float sj = part*invs + cbv;
            if (qd == 0) ps[p*33 + j] = sj;
            tmax = fmaxf(tmax, sj);
        }
        __syncwarp();

        /* online softmax rescale */
        float mn = fmaxf(m, tmax);
        float sc = __expf(m - mn);
        l *= sc;
        u64 sc2; PACK2(sc2, __float_as_uint(sc), __float_as_uint(sc));
#pragma unroll
        for (int c = 0; c < 8; c++) { MUL2(accA[c], accA[c], sc2); MUL2(accB[c], accB[c], sc2); }
        m = mn;

        /* aggregate */
#pragma unroll 2
        for (int j = 0; j < tc; j++) {
            float a = __expf(ps[p*33 + j] - m);
            l += a;
            u64 a2; PACK2(a2, __float_as_uint(a), __float_as_uint(a));
            const ulonglong2* vr = (const ulonglong2*)(vs + j*DIM);
#pragma unroll
            for (int c = 0; c < 8; c++) {
                ulonglong2 vv = vr[c*4 + qd];
                FMA2(accA[c], a2, vv.x, accA[c]);
                FMA2(accB[c], a2, vv.y, accB[c]);
            }
        }
        __syncwarp();
    }

    float inv = (l > 0.f) ? 1.f/l : 0.f;
    u64 inv2; PACK2(inv2, __float_as_uint(inv), __float_as_uint(inv));
    float* ub = U + (size_t)row*512 + h*128;
#pragma unroll
    for (int c = 0; c < 8; c++) {
        MUL2(accA[c], accA[c], inv2);
        MUL2(accB[c], accB[c], inv2);
        ulonglong2 o2; o2.x = accA[c]; o2.y = accB[c];
        *(ulonglong2*)(ub + (c*4 + qd)*4) = o2;
    }
}

/* ------------------- head split-K reduce: relu(sum_z part + b1) ---------- */
__global__ void k_hred(const float* __restrict__ part, const float* __restrict__ b1,
                       float* __restrict__ hh)
{
    int idx = blockIdx.x * blockDim.x + threadIdx.x;   /* 512*128 */
    float s = b1[idx & 127];
#pragma unroll
    for (int z = 0; z < 16; z++) s += part[z*BATCH*DIM + idx];
    hh[idx] = fmaxf(s, 0.f);
}

/* ------------------- final head: dot + softplus -------------------------- */
__global__ void k_head2(const float* __restrict__ hh, const float* __restrict__ w2,
                        const float* __restrict__ b2, float* __restrict__ out)
{
    int b = blockIdx.x*8 + (threadIdx.x >> 5);
    int lane = threadIdx.x & 31;
    if (b >= BATCH) return;
    float4 h4 = *(const float4*)(hh + (size_t)b*DIM + lane*4);
    float4 w4 = *(const float4*)(w2 + lane*4);
    float s = h4.x*w4.x + h4.y*w4.y + h4.z*w4.z + h4.w*w4.w;
#pragma unroll
    for (int o = 16; o > 0; o >>= 1) s += __shfl_xor_sync(0xffffffffu, s, o);
    s += b2[0];
    float sp = fmaxf(s, 0.f) + log1pf(__expf(-fabsf(s)));
    if (lane == 0) out[b] = sp;
}

/* ------------------------------------------------------------------------ */
extern "C" void kernel_launch(void* const* d_in, const int* in_sizes, int n_in,
                              void* d_out, int out_size)
{
    const float* drug_k = (const float*)d_in[0];
    const float* drug_v = (const float*)d_in[1];
    const float* enz_k  = (const float*)d_in[2];
    const float* enz_v  = (const float*)d_in[3];
    const int*   drug_b = (const int*)d_in[4];
    const int*   enz_b  = (const int*)d_in[5];
    const float* latents= (const float*)d_in[6];
    const float* wq_d   = (const float*)d_in[7];
    const float* bq_d   = (const float*)d_in[8];
    const float* wq_e   = (const float*)d_in[9];
    const float* bq_e   = (const float*)d_in[10];
    const float* md_w   = (const float*)d_in[11];
    const float* md_b   = (const float*)d_in[12];
    const float* md_ow  = (const float*)d_in[13];
    const float* md_ob  = (const float*)d_in[14];
    const float* me_w   = (const float*)d_in[15];
    const float* me_b   = (const float*)d_in[16];
    const float* me_ow  = (const float*)d_in[17];
    const float* me_ob  = (const float*)d_in[18];
    const float* ln1g   = (const float*)d_in[19];
    const float* ln1b   = (const float*)d_in[20];
    const float* ln2g   = (const float*)d_in[21];
    const float* ln2b   = (const float*)d_in[22];
    const float* fw1    = (const float*)d_in[23];
    const float* fb1    = (const float*)d_in[24];
    const float* fw2    = (const float*)d_in[25];
    const float* fb2    = (const float*)d_in[26];
    const float* hw1    = (const float*)d_in[27];
    const float* hb1    = (const float*)d_in[28];
    const float* hw2    = (const float*)d_in[29];
    const float* hb2    = (const float*)d_in[30];

    int nD = in_sizes[0] / DIM;
    int nE = in_sizes[2] / DIM;

    float *lat, *nl, *qh, *qtb, *cbv, *Ub, *ob, *f1, *hh, *weff, *beff;
    int *sd, *ldp, *se, *lep;
    cudaGetSymbolAddress((void**)&lat,  g_lat);
    cudaGetSymbolAddress((void**)&nl,   g_nl);
    cudaGetSymbolAddress((void**)&qh,   g_qh);
    cudaGetSymbolAddress((void**)&qtb,  g_qt);
    cudaGetSymbolAddress((void**)&cbv,  g_cb);
    cudaGetSymbolAddress((void**)&Ub,   g_U);
    cudaGetSymbolAddress((void**)&ob,   g_o);
    cudaGetSymbolAddress((void**)&f1,   g_f1);
    cudaGetSymbolAddress((void**)&hh,   g_hh);
    cudaGetSymbolAddress((void**)&weff, g_weff);
    cudaGetSymbolAddress((void**)&beff, g_beff);
    cudaGetSymbolAddress((void**)&sd,   g_sd);
    cudaGetSymbolAddress((void**)&ldp,  g_ldn);
    cudaGetSymbolAddress((void**)&se,   g_se);
    cudaGetSymbolAddress((void**)&lep,  g_len);

    k_bounds<<<2, 256>>>(drug_b, nD, 128, sd, ldp);
    k_bounds<<<2, 256>>>(enz_b,  nE, 512, se, lep);
    k_init<<<ROWS*DIM/256, 256>>>(latents, lat);

    /* fold Weff = Wqq @ Wq per (layer, side); beff = Wqq bq + bq_mha */
    k_gemm<32,128,false,false,false,false><<<dim3(4,1,4), 256>>>(
        md_w, 128, 384*128, wq_d, 128, 128*128, nullptr, 0,
        weff, 128, 2*16384, 128, 128);
    k_gemm<32,128,false,false,false,false><<<dim3(4,1,4), 256>>>(
        me_w, 128, 384*128, wq_e, 128, 128*128, nullptr, 0,
        weff + 16384, 128, 2*16384, 128, 128);
    k_beff<<<dim3(4,2), 128>>>(md_w, me_w, bq_d, bq_e, md_b, me_b, beff);

    for (int l = 0; l < 4; l++) {
        k_ln<<<1024, 256>>>(lat, ln1g + l*128, ln1b + l*128, nl, ROWS);
        for (int s = 0; s < 2; s++) {
            const float* mw  = s ? me_w  : md_w;
            const float* mb  = s ? me_b  : md_b;
            const float* ow  = s ? me_ow : md_ow;
            const float* obv = s ? me_ob : md_ob;
            const float* kr  = s ? enz_k : drug_k;
            const float* vr  = s ? enz_v : drug_v;
            const int*   st  = s ? se : sd;
            const int*   ln  = s ? lep : ldp;
            int pi = l*2 + s;

            /* qh = nl @ Weff^T + beff */
            k_gemm<32,128,true,true,false,false><<<dim3(256,1,1), 256>>>(
                nl, 128, 0, weff + pi*16384, 128, 0, beff + pi*128, 0,
                qh, 128, 0, ROWS, 128);
            /* qt[row,h,:] = Wk_h^T qh_h  (batched over heads, K=32) */
            k_gemm<64,128,false,false,false,false><<<dim3(128,1,4), 256>>>(
                qh, 128, 32, mw + l*384*128 + 128*128, 128, 32*128, nullptr, 0,
                qtb, 512, 128, ROWS, 32);
            k_cbuf<<<128, 256>>>(qh, mb + l*384 + 128, cbv);
            k_attn<<<512, 256>>>(kr, vr, st, ln, qtb, cbv, Ub);
            /* o[.,h*32:] = Wv_h u_h + bv_h  (batched over heads, BN=32) */
            k_gemm<64,32,true,true,false,false><<<dim3(128,1,4), 256>>>(
                Ub, 512, 128, mw + l*384*128 + 256*128, 128, 32*128,
                mb + l*384 + 256, 32, ob, 128, 32, ROWS, 128);
            /* lat += o @ ow^T + ob */
            k_gemm<32,128,true,true,true,false><<<dim3(256,1,1), 256>>>(
                ob, 128, 0, ow + l*16384, 128, 0, obv + l*128, 0,
                lat, 128, 0, ROWS, 128);
        }
        /* FFN */
        k_ln<<<1024, 256>>>(lat, ln2g + l*128, ln2b + l*128, nl, ROWS);
        k_gemm<32,128,true,true,false,true><<<dim3(256,2,1), 256>>>(
            nl, 128, 0, fw1 + l*256*128, 128, 0, fb1 + l*256, 0,
            f1, 256, 0, ROWS, 128);
        k_gemm<32,128,true,true,true,false><<<dim3(256,1,1), 256>>>(
            f1, 256, 0, fw2 + l*128*256, 256, 0, fb2 + l*128, 0,
            lat, 128, 0, ROWS, 256);
    }

    /* head: split-K over the 16 latents into Ub, then reduce+relu, then dot */
    k_gemm<32,128,true,false,false,false><<<dim3(16,1,16), 256>>>(
        lat, 2048, 128, hw1, 2048, 128, nullptr, 0,
        Ub, 128, BATCH*DIM, BATCH, 128);
    k_hred<<<BATCH*DIM/256, 256>>>(Ub, hb1, hh);
    k_head2<<<64, 256>>>(hh, hw2, hb2, (float*)d_out);
}

// round 15
// speedup vs baseline: 1.3401x; 1.1574x over previous
#include <cuda_runtime.h>
#include <math.h>

#define BATCH 512
#define NLAT  16
#define DIM   128
#define ROWS  (BATCH*NLAT)   /* 8192 */

typedef unsigned long long u64;

/* packed fp32x2 ops (sm_100+): per-lane IEEE FMA at 2x FFMA rate */
#define FMA2(d,a,b,c) asm("fma.rn.f32x2 %0, %1, %2, %3;" : "=l"(d) : "l"(a), "l"(b), "l"(c))
#define MUL2(d,a,b)   asm("mul.rn.f32x2 %0, %1, %2;"     : "=l"(d) : "l"(a), "l"(b))
#define ADD2(d,a,b)   asm("add.rn.f32x2 %0, %1, %2;"     : "=l"(d) : "l"(a), "l"(b))
#define PACK2(d,lo,hi) asm("mov.b64 %0, {%1, %2};" : "=l"(d) : "r"(lo), "r"(hi))
#define UNPK2(lo,hi,x) asm("mov.b64 {%0, %1}, %2;" : "=r"(lo), "=r"(hi) : "l"(x))

/* ------------------- scratch (no allocations allowed) ------------------- */
__device__ float g_lat [ROWS*DIM];
__device__ float g_nl  [ROWS*DIM];
__device__ float g_qt  [ROWS*512];
__device__ float g_U   [ROWS*512];     /* also reused as head split-K partials */
__device__ float g_f1  [ROWS*256];
__device__ float g_hh  [BATCH*DIM];
__device__ float g_weff [8*DIM*DIM];
__device__ float g_beff [8*DIM];
__device__ float g_qeff [8*DIM*512];
__device__ float g_meff [8*512*DIM];
__device__ float g_qtbia[8*512];
__device__ float g_beff2[8*DIM];
__device__ float g_wcb  [8*512];
__device__ float g_ccb  [32];
__device__ int   g_sd[BATCH], g_ldn[BATCH], g_se[BATCH], g_len[BATCH];

/* ------------------- segment bounds from sorted batch ids --------------- */
__global__ void k_bounds(const int* __restrict__ batch, int n, int maxlen,
                         int* __restrict__ start, int* __restrict__ len)
{
    int b = blockIdx.x * blockDim.x + threadIdx.x;
    if (b >= BATCH) return;
    int lo = 0, hi = n;
    while (lo < hi) { int mid = (lo + hi) >> 1; if (batch[mid] < b) lo = mid + 1; else hi = mid; }
    int s = lo;
    lo = s; hi = n;
    while (lo < hi) { int mid = (lo + hi) >> 1; if (batch[mid] < b + 1) lo = mid + 1; else hi = mid; }
    int L = lo - s;
    if (L > maxlen) L = maxlen;   /* JAX OOB scatter drops tokens beyond maxlen */
    start[b] = s; len[b] = L;
}

__global__ void k_init(const float* __restrict__ latents, float* __restrict__ lat)
{
    int idx = blockIdx.x * blockDim.x + threadIdx.x;
    if (idx < ROWS*DIM) lat[idx] = latents[idx & (NLAT*DIM - 1)];
}

/* ------------------- LayerNorm, one warp per 128-dim row ---------------- */
__global__ void __launch_bounds__(256) k_ln(const float* __restrict__ x,
                                            const float* __restrict__ g,
                                            const float* __restrict__ bt,
                                            float* __restrict__ y, int M)
{
    int row  = blockIdx.x * 8 + (threadIdx.x >> 5);
    int lane = threadIdx.x & 31;
    if (row >= M) return;
    float4 v = *(const float4*)(x + (size_t)row*DIM + lane*4);
    float s = v.x + v.y + v.z + v.w;
#pragma unroll
    for (int o = 16; o > 0; o >>= 1) s += __shfl_xor_sync(0xffffffffu, s, o);
    float m = s * (1.0f/128.0f);
    float d0 = v.x-m, d1 = v.y-m, d2 = v.z-m, d3 = v.w-m;
    float q = d0*d0 + d1*d1 + d2*d2 + d3*d3;
#pragma unroll
    for (int o = 16; o > 0; o >>= 1) q += __shfl_xor_sync(0xffffffffu, q, o);
    float inv = rsqrtf(q * (1.0f/128.0f) + 1e-5f);
    float4 gg = *(const float4*)(g  + lane*4);
    float4 bb = *(const float4*)(bt + lane*4);
    float4 o4;
    o4.x = d0*inv*gg.x + bb.x;  o4.y = d1*inv*gg.y + bb.y;
    o4.z = d2*inv*gg.z + bb.z;  o4.w = d3*inv*gg.w + bb.w;
    *(float4*)(y + (size_t)row*DIM + lane*4) = o4;
}

/* ------------------- generic fp32 GEMM, f32x2 inner --------------------- */
template<int BM, int BN, bool TRANSW, bool BIAS, bool ACCUM, bool RELU>
__global__ void __launch_bounds__(256)
k_gemm(const float* __restrict__ A, int lda, int aSz,
       const float* __restrict__ W, int ldw, int wSz,
       const float* __restrict__ Bv, int bSz,
       float* __restrict__ C, int ldc, int cSz,
       int M, int K)
{
    constexpr int BK = 32;
    constexpr int TX = BN/4;
    constexpr int TY = 256/TX;
    constexpr int RT = BM/TY;
    constexpr int RP = RT/2;
    static_assert(RT >= 2 && (RT & 1) == 0, "RT must be even");
    constexpr int NA = BM*BK/256;
    constexpr int NW = BN*BK/256;
    __shared__ __align__(16) float As[BK][BM+4];
    __shared__ __align__(16) float Ws[BK][BN+4];

    A += (size_t)blockIdx.z * aSz;
    W += (size_t)blockIdx.z * wSz;
    C += (size_t)blockIdx.z * cSz;
    const float* bias = nullptr;
    if (BIAS) bias = Bv + (size_t)blockIdx.z * bSz;

    int t = threadIdx.x;
    int tx = t % TX, ty = t / TX;
    int mBase = blockIdx.x * BM, nBase = blockIdx.y * BN;

    u64 acc[RP][4];
#pragma unroll
    for (int i = 0; i < RP; i++) { acc[i][0]=0ULL; acc[i][1]=0ULL; acc[i][2]=0ULL; acc[i][3]=0ULL; }

    for (int k0 = 0; k0 < K; k0 += BK) {
#pragma unroll
        for (int u = 0; u < NA; u++) {
            int i = t + u*256;
            int r = i >> 5, c = i & 31;
            As[c][r] = A[(size_t)(mBase + r) * lda + k0 + c];
        }
        if (TRANSW) {
#pragma unroll
            for (int u = 0; u < NW; u++) {
                int i = t + u*256;
                int n = i >> 5, c = i & 31;
                Ws[c][n] = W[(size_t)(nBase + n) * ldw + k0 + c];
            }
        } else {
#pragma unroll
            for (int u = 0; u < NW; u++) {
                int i = t + u*256;
                int c = i / BN, n = i % BN;
                Ws[c][n] = W[(size_t)(k0 + c) * ldw + nBase + n];
            }
        }
        __syncthreads();
#pragma unroll
        for (int kk = 0; kk < BK; kk++) {
            float4 b4 = *(const float4*)&Ws[kk][tx*4];
            u64 bp0, bp1, bp2, bp3;
            PACK2(bp0, __float_as_uint(b4.x), __float_as_uint(b4.x));
            PACK2(bp1, __float_as_uint(b4.y), __float_as_uint(b4.y));
            PACK2(bp2, __float_as_uint(b4.z), __float_as_uint(b4.z));
            PACK2(bp3, __float_as_uint(b4.w), __float_as_uint(b4.w));
#pragma unroll
            for (int i = 0; i < RP; i++) {
                u64 ap = *(const u64*)&As[kk][ty*RT + 2*i];
                FMA2(acc[i][0], ap, bp0, acc[i][0]);
                FMA2(acc[i][1], ap, bp1, acc[i][1]);
                FMA2(acc[i][2], ap, bp2, acc[i][2]);
                FMA2(acc[i][3], ap, bp3, acc[i][3]);
            }
        }
        __syncthreads();
    }

#pragma unroll
    for (int i = 0; i < RP; i++) {
        int m0 = mBase + ty*RT + 2*i;
        int n  = nBase + tx*4;
        float r0[4], r1[4];
#pragma unroll
        for (int c = 0; c < 4; c++) {
            unsigned lo, hi;
            UNPK2(lo, hi, acc[i][c]);
            r0[c] = __uint_as_float(lo);
            r1[c] = __uint_as_float(hi);
        }
        if (BIAS) {
            float4 b4 = *(const float4*)(bias + n);
            r0[0]+=b4.x; r0[1]+=b4.y; r0[2]+=b4.z; r0[3]+=b4.w;
            r1[0]+=b4.x; r1[1]+=b4.y; r1[2]+=b4.z; r1[3]+=b4.w;
        }
        if (ACCUM) {
            float4 c0 = *(const float4*)&C[(size_t)m0*ldc + n];
            float4 c1 = *(const float4*)&C[(size_t)(m0+1)*ldc + n];
            r0[0]+=c0.x; r0[1]+=c0.y; r0[2]+=c0.z; r0[3]+=c0.w;
            r1[0]+=c1.x; r1[1]+=c1.y; r1[2]+=c1.z; r1[3]+=c1.w;
        }
        if (RELU) {
#pragma unroll
            for (int c = 0; c < 4; c++) { r0[c]=fmaxf(r0[c],0.f); r1[c]=fmaxf(r1[c],0.f); }
        }
        *(float4*)&C[(size_t)m0*ldc + n]     = make_float4(r0[0],r0[1],r0[2],r0[3]);
        *(float4*)&C[(size_t)(m0+1)*ldc + n] = make_float4(r1[0],r1[1],r1[2],r1[3]);
    }
}

/* ------------------- beff = Wqq @ bq + bq_mha ---------------------------- */
__global__ void k_beff(const float* md_w, const float* me_w,
                       const float* bqd, const float* bqe,
                       const float* mdb, const float* meb, float* beff)
{
    int l = blockIdx.x, s = blockIdx.y, n = threadIdx.x;
    const float* wqq = (s ? me_w : md_w) + l*384*128;
    const float* bq  = (s ? bqe  : bqd ) + l*128;
    const float* bm  = (s ? meb  : mdb ) + l*384;
    float v = bm[n];
    for (int j = 0; j < 128; j++) v += wqq[n*128 + j]*bq[j];
    beff[(l*2 + s)*128 + n] = v;
}

/* ------------------- fold: OUT[a,b] = sum_j X[j*128+a]*Y(j,b) ------------ */
/* TR=false: Y(j,b)=Y[j*128+b];  TR=true: Y(j,b)=Y[b*128+j].                */
/* blockIdx.x = z = l*4+h.  Per-z offsets: base + l*?l + h*?h.              */
template<bool TR>
__global__ void __launch_bounds__(256) k_fold(
    const float* __restrict__ X, int xl, int xh,
    const float* __restrict__ Y, int yl, int yh,
    float* __restrict__ OUT, int ol, int oh, int ldo)
{
    int l = blockIdx.x >> 2, h = blockIdx.x & 3;
    X   += (size_t)l*xl + (size_t)h*xh;
    Y   += (size_t)l*yl + (size_t)h*yh;
    OUT += (size_t)l*ol + (size_t)h*oh;
    __shared__ float Xs[32][132], Ys[32][132];
    int t = threadIdx.x;
    for (int i = t; i < 32*128; i += 256) {
        int j = i >> 7, a = i & 127;
        Xs[j][a] = X[j*128 + a];
        Ys[j][a] = TR ? Y[a*128 + j] : Y[j*128 + a];
    }
    __syncthreads();
    int a  = t >> 1;
    int b0 = (t & 1) * 64;
    for (int bc = 0; bc < 64; bc += 16) {
        float acc[16];
#pragma unroll
        for (int q = 0; q < 16; q++) acc[q] = 0.f;
        for (int j = 0; j < 32; j++) {
            float xa = Xs[j][a];
#pragma unroll
            for (int q = 0; q < 16; q++) acc[q] += xa * Ys[j][b0+bc+q];
        }
#pragma unroll
        for (int q = 0; q < 16; q++) OUT[a*ldo + b0+bc+q] = acc[q];
    }
}

/* qtbias[pi, h*128+c] = sum_j Wk[h*32+j, c] * beff[pi, h*32+j] */
__global__ void k_qtb(const float* md_w, const float* me_w,
                      const float* beff, float* qtbias)
{
    int l = blockIdx.x, s = blockIdx.y, t = threadIdx.x;  /* 512 threads */
    int pi = l*2 + s;
    const float* mw = (s ? me_w : md_w) + l*384*128 + 128*128;
    int h = t >> 7, c = t & 127;
    const float* be = beff + pi*128 + h*32;
    float v = 0.f;
    for (int j = 0; j < 32; j++) v += mw[(h*32+j)*128 + c] * be[j];
    qtbias[pi*512 + t] = v;
}

/* beff2[pi, n] = ob[n] + sum_m ow[n,m]*bv[m] */
__global__ void k_b2(const float* md_ow, const float* me_ow,
                     const float* md_b, const float* me_b,
                     const float* md_ob, const float* me_ob, float* beff2)
{
    int l = blockIdx.x, s = blockIdx.y, n = threadIdx.x;
    const float* ow = (s ? me_ow : md_ow) + l*16384 + n*128;
    const float* bv = (s ? me_b  : md_b ) + l*384 + 256;
    const float* ob = (s ? me_ob : md_ob) + l*128;
    float v = ob[n];
    for (int m = 0; m < 128; m++) v += ow[m]*bv[m];
    beff2[(l*2+s)*128 + n] = v;
}

/* wcb[pi, h*128+d] = sum_j Weff[pi, h*32+j, d]*bk[h*32+j]; ccb = beff.bk  */
__global__ void k_wcb(const float* md_b, const float* me_b,
                      const float* weff, const float* beff,
                      float* wcb, float* ccb)
{
    int l = blockIdx.x, s = blockIdx.y, t = threadIdx.x;  /* 512 threads */
    int pi = l*2 + s;
    const float* bk = (s ? me_b : md_b) + l*384 + 128;
    int h = t >> 7, d = t & 127;
    const float* wf = weff + pi*16384 + h*32*128;
    float v = 0.f;
    for (int j = 0; j < 32; j++) v += wf[j*128 + d] * bk[h*32 + j];
    wcb[pi*512 + t] = v;
    if (t < 4) {
        float c = 0.f;
        const float* be = beff + pi*128 + t*32;
        for (int j = 0; j < 32; j++) c += be[j] * bk[t*32 + j];
        ccb[pi*4 + t] = c;
    }
}

/* ------------------- flash cross-attention over raw segments ------------- */
/* 256 threads = 32 groups x 8 lanes.  Group g owns pairs 2g, 2g+1 (same    */
/* latent, heads h,h+1).  Lane qd owns 16 dims; each k/v LDS feeds 2 pairs. */
__global__ void __launch_bounds__(256, 2)
k_attn(const float* __restrict__ kraw, const float* __restrict__ vraw,
       const int* __restrict__ starts, const int* __restrict__ lens,
       const float* __restrict__ qt, const float* __restrict__ nl,
       const float* __restrict__ wcb, const float* __restrict__ ccb,
       int pi, float* __restrict__ U)
{
    __shared__ __align__(16) float ks[32*DIM];
    __shared__ __align__(16) float vs[32*DIM];
    __shared__ float ps[64*33];
    const float invs = 0.17677669529663687f;  /* 1/sqrt(32) */
    int b = blockIdx.x;
    int t = threadIdx.x;
    int g = t >> 3, qd = t & 7;
    int p0 = 2*g, p1 = 2*g + 1;
    int i0 = p0 >> 2, h0 = p0 & 3;            /* h1 = h0+1, same latent */
    int row = b*NLAT + i0;

    /* q regs: 4 chunks of 16B at chunk index c*8+qd */
    const float* qb0 = qt + (size_t)row*512 + h0*128;
    u64 q0[8], q1[8];
#pragma unroll
    for (int c = 0; c < 4; c++) {
        ulonglong2 a = *(const ulonglong2*)(qb0 + (c*8 + qd)*4);
        ulonglong2 d = *(const ulonglong2*)(qb0 + 128 + (c*8 + qd)*4);
        q0[2*c] = a.x; q0[2*c+1] = a.y;
        q1[2*c] = d.x; q1[2*c+1] = d.y;
    }

    /* inline cb = nl . wcb + ccb */
    float cb0, cb1;
    {
        const float* nlr = nl + (size_t)row*DIM;
        const float* w0  = wcb + pi*512 + h0*128;
        float pa = 0.f, pb = 0.f;
#pragma unroll
        for (int c = 0; c < 4; c++) {
            int d0 = (c*8 + qd)*4;
#pragma unroll
            for (int e = 0; e < 4; e++) {
                float nv = nlr[d0+e];
                pa += nv * w0[d0+e];
                pb += nv * w0[128 + d0+e];
            }
        }
#pragma unroll
        for (int o = 1; o < 8; o <<= 1) {
            pa += __shfl_xor_sync(0xffffffffu, pa, o);
            pb += __shfl_xor_sync(0xffffffffu, pb, o);
        }
        cb0 = (pa + ccb[pi*4 + h0]) * invs;
        cb1 = (pb + ccb[pi*4 + h0 + 1]) * invs;
    }

    int s0 = starts[b], L = lens[b];
    u64 acc0[8], acc1[8];
#pragma unroll
    for (int c = 0; c < 8; c++) { acc0[c] = 0ULL; acc1[c] = 0ULL; }
    float m0 = -1e30f, l0 = 0.f, m1 = -1e30f, l1 = 0.f;

    for (int j0 = 0; j0 < L; j0 += 32) {
        int tc = min(32, L - j0);
        __syncthreads();
#pragma unroll
        for (int u = 0; u < 4; u++) {
            int i = t + u*256;
            int j = i >> 5, c4 = i & 31;
            if (j < tc) {
                const float4* gk = (const float4*)(kraw + (size_t)(s0 + j0 + j)*DIM);
                const float4* gv = (const float4*)(vraw + (size_t)(s0 + j0 + j)*DIM);
                ((float4*)ks)[i] = gk[c4];
                ((float4*)vs)[i] = gv[c4];
            }
        }
        __syncthreads();

        /* scores: S[2 pairs, j] over 128 dims, k LDS shared by both pairs */
        float tm0 = -1e30f, tm1 = -1e30f;
        for (int j = 0; j < tc; j++) {
            const ulonglong2* kr = (const ulonglong2*)(ks + j*DIM);
            u64 pa = 0ULL, pb = 0ULL;
#pragma unroll
            for (int c = 0; c < 4; c++) {
                ulonglong2 kk = kr[c*8 + qd];
                FMA2(pa, q0[2*c],   kk.x, pa);
                FMA2(pa, q0[2*c+1], kk.y, pa);
                FMA2(pb, q1[2*c],   kk.x, pb);
                FMA2(pb, q1[2*c+1], kk.y, pb);
            }
            unsigned lo, hi;
            UNPK2(lo, hi, pa);
            float part0 = __uint_as_float(lo) + __uint_as_float(hi);
            UNPK2(lo, hi, pb);
            float part1 = __uint_as_float(lo) + __uint_as_float(hi);
#pragma unroll
            for (int o = 1; o < 8; o <<= 1) {
                part0 += __shfl_xor_sync(0xffffffffu, part0, o);
                part1 += __shfl_xor_sync(0xffffffffu, part1, o);
            }
            float sj0 = part0*invs + cb0;
            float sj1 = part1*invs + cb1;
            if (qd == 0) { ps[p0*33 + j] = sj0; ps[p1*33 + j] = sj1; }
            tm0 = fmaxf(tm0, sj0);
            tm1 = fmaxf(tm1, sj1);
        }
        __syncwarp();

        /* online softmax rescale */
        float mn0 = fmaxf(m0, tm0), mn1 = fmaxf(m1, tm1);
        float sc0 = __expf(m0 - mn0), sc1 = __expf(m1 - mn1);
        l0 *= sc0; l1 *= sc1;
        u64 s02, s12;
        PACK2(s02, __float_as_uint(sc0), __float_as_uint(sc0));
        PACK2(s12, __float_as_uint(sc1), __float_as_uint(sc1));
#pragma unroll
        for (int c = 0; c < 8; c++) { MUL2(acc0[c], acc0[c], s02); MUL2(acc1[c], acc1[c], s12); }
        m0 = mn0; m1 = mn1;

        /* aggregate: v LDS shared by both pairs */
        for (int j = 0; j < tc; j++) {
            float a0 = __expf(ps[p0*33 + j] - m0);
            float a1 = __expf(ps[p1*33 + j] - m1);
            l0 += a0; l1 += a1;
            u64 a02, a12;
            PACK2(a02, __float_as_uint(a0), __float_as_uint(a0));
            PACK2(a12, __float_as_uint(a1), __float_as_uint(a1));
            const ulonglong2* vr = (const ulonglong2*)(vs + j*DIM);
#pragma unroll
            for (int c = 0; c < 4; c++) {
                ulonglong2 vv = vr[c*8 + qd];
                FMA2(acc0[2*c],   a02, vv.x, acc0[2*c]);
                FMA2(acc0[2*c+1], a02, vv.y, acc0[2*c+1]);
                FMA2(acc1[2*c],   a12, vv.x, acc1[2*c]);
                FMA2(acc1[2*c+1], a12, vv.y, acc1[2*c+1]);
            }
        }
        __syncwarp();
    }

    float inv0 = (l0 > 0.f) ? 1.f/l0 : 0.f;
    float inv1 = (l1 > 0.f) ? 1.f/l1 : 0.f;
    u64 i02, i12;
    PACK2(i02, __float_as_uint(inv0), __float_as_uint(inv0));
    PACK2(i12, __float_as_uint(inv1), __float_as_uint(inv1));
    float* ub = U + (size_t)row*512 + h0*128;
#pragma unroll
    for (int c = 0; c < 4; c++) {
        ulonglong2 o0, o1;
        MUL2(o0.x, acc0[2*c],   i02); MUL2(o0.y, acc0[2*c+1], i02);
        MUL2(o1.x, acc1[2*c],   i12); MUL2(o1.y, acc1[2*c+1], i12);
        *(ulonglong2*)(ub + (c*8 + qd)*4)       = o0;
        *(ulonglong2*)(ub + 128 + (c*8 + qd)*4) = o1;
    }
}

/* ------------------- head split-K reduce: relu(sum_z part + b1) ---------- */
__global__ void k_hred(const float* __restrict__ part, const float* __restrict__ b1,
                       float* __restrict__ hh)
{
    int idx = blockIdx.x * blockDim.x + threadIdx.x;   /* 512*128 */
    float s = b1[idx & 127];
#pragma unroll
    for (int z = 0; z < 16; z++) s += part[z*BATCH*DIM + idx];
    hh[idx] = fmaxf(s, 0.f);
}

/* ------------------- final head: dot + softplus -------------------------- */
__global__ void k_head2(const float* __restrict__ hh, const float* __restrict__ w2,
                        const float* __restrict__ b2, float* __restrict__ out)
{
    int b = blockIdx.x*8 + (threadIdx.x >> 5);
    int lane = threadIdx.x & 31;
    if (b >= BATCH) return;
    float4 h4 = *(const float4*)(hh + (size_t)b*DIM + lane*4);
    float4 w4 = *(const float4*)(w2 + lane*4);
    float s = h4.x*w4.x + h4.y*w4.y + h4.z*w4.z + h4.w*w4.w;
#pragma unroll
    for (int o = 16; o > 0; o >>= 1) s += __shfl_xor_sync(0xffffffffu, s, o);
    s += b2[0];
    float sp = fmaxf(s, 0.f) + log1pf(__expf(-fabsf(s)));
    if (lane == 0) out[b] = sp;
}

/* ------------------------------------------------------------------------ */
extern "C" void kernel_launch(void* const* d_in, const int* in_sizes, int n_in,
                              void* d_out, int out_size)
{
    const float* drug_k = (const float*)d_in[0];
    const float* drug_v = (const float*)d_in[1];
    const float* enz_k  = (const float*)d_in[2];
    const float* enz_v  = (const float*)d_in[3];
    const int*   drug_b = (const int*)d_in[4];
    const int*   enz_b  = (const int*)d_in[5];
    const float* latents= (const float*)d_in[6];
    const float* wq_d   = (const float*)d_in[7];
    const float* bq_d   = (const float*)d_in[8];
    const float* wq_e   = (const float*)d_in[9];
    const float* bq_e   = (const float*)d_in[10];
    const float* md_w   = (const float*)d_in[11];
    const float* md_b   = (const float*)d_in[12];
    const float* md_ow  = (const float*)d_in[13];
    const float* md_ob  = (const float*)d_in[14];
    const float* me_w   = (const float*)d_in[15];
    const float* me_b   = (const float*)d_in[16];
    const float* me_ow  = (const float*)d_in[17];
    const float* me_ob  = (const float*)d_in[18];
    const float* ln1g   = (const float*)d_in[19];
    const float* ln1b   = (const float*)d_in[20];
    const float* ln2g   = (const float*)d_in[21];
    const float* ln2b   = (const float*)d_in[22];
    const float* fw1    = (const float*)d_in[23];
    const float* fb1    = (const float*)d_in[24];
    const float* fw2    = (const float*)d_in[25];
    const float* fb2    = (const float*)d_in[26];
    const float* hw1    = (const float*)d_in[27];
    const float* hb1    = (const float*)d_in[28];
    const float* hw2    = (const float*)d_in[29];
    const float* hb2    = (const float*)d_in[30];

    int nD = in_sizes[0] / DIM;
    int nE = in_sizes[2] / DIM;

    float *lat, *nl, *qtb, *Ub, *f1, *hh, *weff, *beff;
    float *qeff, *meff, *qtbias, *beff2, *wcb, *ccb;
    int *sd, *ldp, *se, *lep;
    cudaGetSymbolAddress((void**)&lat,   g_lat);
    cudaGetSymbolAddress((void**)&nl,    g_nl);
    cudaGetSymbolAddress((void**)&qtb,   g_qt);
    cudaGetSymbolAddress((void**)&Ub,    g_U);
    cudaGetSymbolAddress((void**)&f1,    g_f1);
    cudaGetSymbolAddress((void**)&hh,    g_hh);
    cudaGetSymbolAddress((void**)&weff,  g_weff);
    cudaGetSymbolAddress((void**)&beff,  g_beff);
    cudaGetSymbolAddress((void**)&qeff,  g_qeff);
    cudaGetSymbolAddress((void**)&meff,  g_meff);
    cudaGetSymbolAddress((void**)&qtbias,g_qtbia);
    cudaGetSymbolAddress((void**)&beff2, g_beff2);
    cudaGetSymbolAddress((void**)&wcb,   g_wcb);
    cudaGetSymbolAddress((void**)&ccb,   g_ccb);
    cudaGetSymbolAddress((void**)&sd,    g_sd);
    cudaGetSymbolAddress((void**)&ldp,   g_ldn);
    cudaGetSymbolAddress((void**)&se,    g_se);
    cudaGetSymbolAddress((void**)&lep,   g_len);

    k_bounds<<<2, 256>>>(drug_b, nD, 128, sd, ldp);
    k_bounds<<<2, 256>>>(enz_b,  nE, 512, se, lep);
    k_init<<<ROWS*DIM/256, 256>>>(latents, lat);

    /* Weff = Wq_mha @ Wq per (layer, side); beff = Wq_mha bq + bq_mha */
    k_gemm<32,128,false,false,false,false><<<dim3(4,1,4), 256>>>(
        md_w, 128, 384*128, wq_d, 128, 128*128, nullptr, 0,
        weff, 128, 2*16384, 128, 128);
    k_gemm<32,128,false,false,false,false><<<dim3(4,1,4), 256>>>(
        me_w, 128, 384*128, wq_e, 128, 128*128, nullptr, 0,
        weff + 16384, 128, 2*16384, 128, 128);
    k_beff<<<dim3(4,2), 128>>>(md_w, me_w, bq_d, bq_e, md_b, me_b, beff);

    /* Qeff[pi][din, h*128+c] = sum_j Weff[h*32+j,din] * Wk[h*32+j,c] */
    k_fold<false><<<16, 256>>>(weff,           32768, 4096,
                               md_w + 128*128, 49152, 4096,
                               qeff,          131072, 128, 512);
    k_fold<false><<<16, 256>>>(weff + 16384,   32768, 4096,
                               me_w + 128*128, 49152, 4096,
                               qeff + 65536,  131072, 128, 512);
    /* Meff[pi][h*128+c, n] = sum_j Wv[h*32+j,c] * ow[n, h*32+j] */
    k_fold<true><<<16, 256>>>(md_w + 256*128, 49152, 4096,
                              md_ow,          16384, 32,
                              meff,          131072, 16384, 128);
    k_fold<true><<<16, 256>>>(me_w + 256*128, 49152, 4096,
                              me_ow,          16384, 32,
                              meff + 65536,  131072, 16384, 128);
    k_qtb<<<dim3(4,2), 512>>>(md_w, me_w, beff, qtbias);
    k_b2 <<<dim3(4,2), 128>>>(md_ow, me_ow, md_b, me_b, md_ob, me_ob, beff2);
    k_wcb<<<dim3(4,2), 512>>>(md_b, me_b, weff, beff, wcb, ccb);

    for (int l = 0; l < 4; l++) {
        k_ln<<<1024, 256>>>(lat, ln1g + l*128, ln1b + l*128, nl, ROWS);
        for (int s = 0; s < 2; s++) {
            const float* kr = s ? enz_k : drug_k;
            const float* vr = s ? enz_v : drug_v;
            const int*   st = s ? se : sd;
            const int*   lp = s ? lep : ldp;
            int pi = l*2 + s;

            /* qt = nl @ Qeff + qtbias   [8192,128]->[8192,512] */
            k_gemm<32,128,false,true,false,false><<<dim3(256,4,1), 256>>>(
                nl, 128, 0, qeff + pi*65536, 512, 0, qtbias + pi*512, 0,
                qtb, 512, 0, ROWS, 128);
            k_attn<<<512, 256>>>(kr, vr, st, lp, qtb, nl, wcb, ccb, pi, Ub);
            /* lat += U @ Meff + beff2   [8192,512]->[8192,128] */
            k_gemm<32,128,false,true,true,false><<<dim3(256,1,1), 256>>>(
                Ub, 512, 0, meff + pi*65536, 128, 0, beff2 + pi*128, 0,
                lat, 128, 0, ROWS, 512);
        }
        /* FFN */
        k_ln<<<1024, 256>>>(lat, ln2g + l*128, ln2b + l*128, nl, ROWS);
        k_gemm<32,128,true,true,false,true><<<dim3(256,2,1), 256>>>(
            nl, 128, 0, fw1 + l*256*128, 128, 0, fb1 + l*256, 0,
            f1, 256, 0, ROWS, 128);
        k_gemm<32,128,true,true,true,false><<<dim3(256,1,1), 256>>>(
            f1, 256, 0, fw2 + l*128*256, 256, 0, fb2 + l*128, 0,
            lat, 128, 0, ROWS, 256);
    }

    /* head: split-K over the 16 latents into Ub, then reduce+relu, then dot */
    k_gemm<32,128,true,false,false,false><<<dim3(16,1,16), 256>>>(
        lat, 2048, 128, hw1, 2048, 128, nullptr, 0,
        Ub, 128, BATCH*DIM, BATCH, 128);
    k_hred<<<BATCH*DIM/256, 256>>>(Ub, hb1, hh);
    k_head2<<<64, 256>>>(hh, hw2, hb2, (float*)d_out);
}